// round 7
// baseline (speedup 1.0000x reference)
#include <cuda_runtime.h>
#include <math.h>

#define Hh   128
#define NPRc 3000
#define EPRc 6000
#define NTOT 48000
#define NCc  512     // C columns: [0,384) iou_x, [384,512) wf_x
#define RBLK 296     // k_round grid: 2 blocks/SM

// static scratch (no allocations allowed)
__device__ float g_C[(size_t)NTOT * NCc];   // 98.3 MB
__device__ float g_c[(size_t)NTOT * Hh];    // 24.6 MB
__device__ float g_Ut[256 * 512];           // U^T: [k][row]  (row<384: U_iou, else U_f)
__device__ float g_Wt[128 * 512];           // W^T: [k][row]  (row<384: W_iou, else W_f)

union F2U { float2 f; unsigned long long u; };
__device__ __forceinline__ float2 ffma2(float2 a, float2 b, float2 c) {
    F2U A, B, C2, D;
    A.f = a; B.f = b; C2.f = c;
    asm("fma.rn.f32x2 %0, %1, %2, %3;" : "=l"(D.u) : "l"(A.u), "l"(B.u), "l"(C2.u));
    return D.f;
}
__device__ __forceinline__ float2 spl(float b) { return make_float2(b, b); }
__device__ __forceinline__ float sigf(float x) { return 1.0f / (1.0f + expf(-x)); }

// ---------------------------------------------------------------------------
// One-shot weight transposes, merged (writes coalesced). grid 768.
// ---------------------------------------------------------------------------
__global__ __launch_bounds__(256) void k_trans(const float* __restrict__ U_iou,
                                               const float* __restrict__ U_f,
                                               const float* __restrict__ W_iou,
                                               const float* __restrict__ W_f) {
    int b = blockIdx.x;
    if (b < 512) {
        int idx = b * 256 + threadIdx.x;               // 131072
        int k = idx >> 9, row = idx & 511;
        g_Ut[idx] = (row < 384) ? U_iou[row * 256 + k] : U_f[(row - 384) * 256 + k];
    } else {
        int idx = (b - 512) * 256 + threadIdx.x;       // 65536
        int k = idx >> 9, row = idx & 511;
        g_Wt[idx] = (row < 384) ? W_iou[row * 128 + k] : W_f[(row - 384) * 128 + k];
    }
}

// ---------------------------------------------------------------------------
// k_pre: C[n][0:384] = x @ W_iou^T ; C[n][384:512] = x @ W_f^T
// Tiled GEMM: 32 rows x 512 cols per block, K=128. grid 1500, 2 blocks/SM.
// B loads coalesced from g_Wt. 16 chunks x 8 k, double-buffered.
// smem floats: A[128*36] @0 | Bs[2*8*512] @4608 | xs[32*132] @12800 = 17024
// ---------------------------------------------------------------------------
#define PRE_SMEMB (17024 * 4)

__global__ __launch_bounds__(256, 2) void k_pre(const float* __restrict__ x) {
    extern __shared__ float sm[];
    float* A  = sm;           // [k][row], stride 36
    float* Bs = sm + 4608;    // [buf][kk][512]
    float* xs = sm + 12800;   // [row][132]
    int t  = threadIdx.x;
    int r0 = blockIdx.x * 32;

#pragma unroll
    for (int j = 0; j < 4; j++) {                      // stage x coalesced
        int f = t + 256 * j, row = f >> 5, q = f & 31;
        *(float4*)&xs[row * 132 + 4 * q] = *((const float4*)(x + (size_t)(r0 + row) * 128) + q);
    }
    __syncthreads();
#pragma unroll
    for (int j = 0; j < 4; j++) {                      // transpose -> A[k][row]
        int f = t + 256 * j, row = f & 31, q = f >> 5;
        float4 v = *(const float4*)&xs[row * 132 + 4 * q];
        A[(4 * q + 0) * 36 + row] = v.x; A[(4 * q + 1) * 36 + row] = v.y;
        A[(4 * q + 2) * 36 + row] = v.z; A[(4 * q + 3) * 36 + row] = v.w;
    }
#pragma unroll
    for (int j = 0; j < 4; j++) {                      // B chunk 0 (k=0..7), coalesced
        int f = t + 256 * j, ks = f >> 7, c4 = (f & 127) * 4;
        *(float4*)&Bs[ks * 512 + c4] = *(const float4*)&g_Wt[ks * 512 + c4];
    }
    __syncthreads();

    int ct = t & 127;            // cols ct, 128+ct, 256+ct, 384+ct
    int rb = (t >> 7) * 16;      // 16 rows
    float2 acc[4][8];
#pragma unroll
    for (int cc = 0; cc < 4; cc++)
#pragma unroll
        for (int r = 0; r < 8; r++) acc[cc][r] = make_float2(0.f, 0.f);

#pragma unroll 1
    for (int c = 0; c < 16; c++) {                     // 16 chunks x 8 k
        float4 nb[4];
        if (c < 15) {
#pragma unroll
            for (int j = 0; j < 4; j++) {
                int f = t + 256 * j, ks = f >> 7, c4 = (f & 127) * 4;
                nb[j] = *(const float4*)&g_Wt[((c + 1) * 8 + ks) * 512 + c4];
            }
        }
        const float* Bb = Bs + (c & 1) * 4096;
#pragma unroll
        for (int kk = 0; kk < 8; kk++) {
            int kg = c * 8 + kk;
            float2 b0 = spl(Bb[kk * 512 + ct]);
            float2 b1 = spl(Bb[kk * 512 + 128 + ct]);
            float2 b2 = spl(Bb[kk * 512 + 256 + ct]);
            float2 b3 = spl(Bb[kk * 512 + 384 + ct]);
            const float* ap = A + kg * 36 + rb;
#pragma unroll
            for (int g4 = 0; g4 < 4; g4++) {
                float4 av = *(const float4*)(ap + 4 * g4);
                float2 p0 = make_float2(av.x, av.y), p1 = make_float2(av.z, av.w);
                acc[0][2*g4]   = ffma2(b0, p0, acc[0][2*g4]);
                acc[0][2*g4+1] = ffma2(b0, p1, acc[0][2*g4+1]);
                acc[1][2*g4]   = ffma2(b1, p0, acc[1][2*g4]);
                acc[1][2*g4+1] = ffma2(b1, p1, acc[1][2*g4+1]);
                acc[2][2*g4]   = ffma2(b2, p0, acc[2][2*g4]);
                acc[2][2*g4+1] = ffma2(b2, p1, acc[2][2*g4+1]);
                acc[3][2*g4]   = ffma2(b3, p0, acc[3][2*g4]);
                acc[3][2*g4+1] = ffma2(b3, p1, acc[3][2*g4+1]);
            }
        }
        if (c < 15) {
            float* d = Bs + ((c + 1) & 1) * 4096;
#pragma unroll
            for (int j = 0; j < 4; j++) {
                int f = t + 256 * j, ks = f >> 7, c4 = (f & 127) * 4;
                *(float4*)&d[ks * 512 + c4] = nb[j];
            }
            __syncthreads();
        }
    }
#pragma unroll
    for (int cc = 0; cc < 4; cc++) {                   // grid*32 == 48000, no guard
        int col = ct + 128 * cc;
#pragma unroll
        for (int r = 0; r < 8; r++) {
            int row = r0 + rb + 2 * r;
            g_C[(size_t)row * NCc + col]       = acc[cc][r].x;
            g_C[(size_t)(row + 1) * NCc + col] = acc[cc][r].y;
        }
    }
}

// ---------------------------------------------------------------------------
// Round 0: leaves. iou_mid = 0, c = 0.
// ---------------------------------------------------------------------------
__global__ __launch_bounds__(256) void k_round0(float* __restrict__ h,
                                                const int* __restrict__ order0,
                                                const float* __restrict__ b_iou) {
    int idx = blockIdx.x * 256 + threadIdx.x;
    if (idx >= NPRc * Hh) return;
    int j = idx >> 7, m = idx & 127;
    int node = order0[j];
    const float* Cp = g_C + (size_t)node * NCc;
    float gi = Cp[m]       + b_iou[m];
    float go = Cp[128 + m] + b_iou[128 + m];
    float gu = Cp[256 + m] + b_iou[256 + m];
    float ct = sigf(gi) * tanhf(gu);
    g_c[(size_t)node * Hh + m] = ct;
    h[(size_t)node * Hh + m]   = sigf(go) * tanhf(ct);
}

// ---------------------------------------------------------------------------
// One topological round. grid 296 x 256 thr = 2 blocks/SM (phase overlap);
// ~10-11 parents/block padded to 12. A-tile [stream][k][12]: s0=gsum,
// s1=he2_a, s2=he2_b. B = 512 weight rows from g_Ut, double-buffered 16-k.
// Thread (ct = t&127, pg = (t>>7)*6): 5 col-streams x 6 parents, 15 FFMA2/k.
// A-tile reads float2 (pg even -> 8B aligned; float4 would trap at pg=6).
// smem floats: As 9216 @0 | Bs 16384 @9216 = 25600 (hs alias Bs; epi alias As)
// ---------------------------------------------------------------------------
#define RND_SMEMB (25600 * 4)

__global__ __launch_bounds__(256, 2) void k_round(int ri, float* __restrict__ h,
        const float* __restrict__ b_iou, const float* __restrict__ b_f,
        const int* __restrict__ edges_r, const float* __restrict__ labels) {
    extern __shared__ float sm[];
    float* As  = sm;            // 3*256*12 = 9216
    float* Bs  = sm + 9216;     // 2*16*512 = 16384
    float* hs  = Bs;            // staging alias (24*132 = 3168 <= 16384)
    float* epi = sm;            // alias after GEMM (12*640 = 7680 <= 9216)
    __shared__ int s_child[24], s_lab[24], s_par[12];

    int t  = threadIdx.x;
    int p0 = ((int)blockIdx.x * NPRc) / RBLK;
    int p1 = (((int)blockIdx.x + 1) * NPRc) / RBLK;
    int np = p1 - p0;           // 10 or 11

    const int*   e_src   = edges_r + ri * 2 * EPRc;
    const int*   e_child = e_src + EPRc;
    const float* labp    = labels + ri * EPRc;

    if (t < 24) {
        int ok = t < 2 * np;
        int e = 2 * p0 + t;
        s_child[t] = ok ? e_child[e] : 0;
        s_lab[t]   = ok ? (labp[e] != 0.0f ? 1 : 0) : 0;
    }
    if (t >= 32 && t < 44) {
        int pp = t - 32;
        s_par[pp] = (pp < np) ? e_src[2 * (p0 + pp)] : 0;
    }
    __syncthreads();

    // stage 24 child h-rows coalesced
#pragma unroll
    for (int j = 0; j < 3; j++) {
        int f = t + 256 * j, e = f >> 5, q = f & 31;
        *(float4*)&hs[e * 132 + 4 * q] = *((const float4*)(h + (size_t)s_child[e] * Hh) + q);
    }
    __syncthreads();
    // scatter into As streams 1,2 with zero complement (k-major, stride 12)
#pragma unroll
    for (int j = 0; j < 3; j++) {
        int f = t + 256 * j, e = f % 24, q = f / 24;   // q in [0,32)
        float4 v = *(const float4*)&hs[e * 132 + 4 * q];
        int p = e >> 1, eo = e & 1, lab = s_lab[e];
        int bh = ((1 + eo) * 256 + lab * 128 + 4 * q) * 12 + p;
        int bz = ((1 + eo) * 256 + (1 - lab) * 128 + 4 * q) * 12 + p;
        As[bh] = v.x; As[bh + 12] = v.y; As[bh + 24] = v.z; As[bh + 36] = v.w;
        As[bz] = 0.f; As[bz + 12] = 0.f; As[bz + 24] = 0.f; As[bz + 36] = 0.f;
    }
    __syncthreads();            // hs (Bs alias) dead from here
    // stream0 = gsum = he2_a + he2_b
#pragma unroll
    for (int j = 0; j < 3; j++) {
        int f = t + 256 * j, k = f / 3, pq = (f % 3) * 4;
        float4 a = *(const float4*)&As[(256 + k) * 12 + pq];
        float4 b = *(const float4*)&As[(512 + k) * 12 + pq];
        *(float4*)&As[k * 12 + pq] = make_float4(a.x + b.x, a.y + b.y, a.z + b.z, a.w + b.w);
    }
    // B chunk 0 (k=0..15), coalesced
#pragma unroll
    for (int j = 0; j < 8; j++) {
        int f = t + 256 * j, ks = f >> 7, c4 = (f & 127) * 4;
        *(float4*)&Bs[ks * 512 + c4] = *(const float4*)&g_Ut[ks * 512 + c4];
    }
    __syncthreads();

    int ct = t & 127;
    int pg = (t >> 7) * 6;
    const float* Ag = As;
    const float* Aa = As + 3072;
    const float* Ab = As + 6144;
    float2 acc[5][3];
#pragma unroll
    for (int s5 = 0; s5 < 5; s5++)
#pragma unroll
        for (int pr = 0; pr < 3; pr++) acc[s5][pr] = make_float2(0.f, 0.f);

#pragma unroll 1
    for (int c = 0; c < 16; c++) {                     // 16 chunks x 16 k
        float4 nb[8];
        if (c < 15) {
#pragma unroll
            for (int j = 0; j < 8; j++) {
                int f = t + 256 * j, ks = f >> 7, c4 = (f & 127) * 4;
                nb[j] = *(const float4*)&g_Ut[((c + 1) * 16 + ks) * 512 + c4];
            }
        }
        const float* Bb = Bs + (c & 1) * 8192;
#pragma unroll
        for (int kk = 0; kk < 16; kk++) {
            int kg = c * 16 + kk;
            float2 b0 = spl(Bb[kk * 512 + ct]);
            float2 b1 = spl(Bb[kk * 512 + 128 + ct]);
            float2 b2 = spl(Bb[kk * 512 + 256 + ct]);
            float2 b3 = spl(Bb[kk * 512 + 384 + ct]);
            int off = kg * 12 + pg;
            float2 q0 = *(const float2*)(Ag + off);
            float2 q1 = *(const float2*)(Ag + off + 2);
            float2 q2 = *(const float2*)(Ag + off + 4);
            acc[0][0] = ffma2(b0, q0, acc[0][0]);
            acc[0][1] = ffma2(b0, q1, acc[0][1]);
            acc[0][2] = ffma2(b0, q2, acc[0][2]);
            acc[1][0] = ffma2(b1, q0, acc[1][0]);
            acc[1][1] = ffma2(b1, q1, acc[1][1]);
            acc[1][2] = ffma2(b1, q2, acc[1][2]);
            acc[2][0] = ffma2(b2, q0, acc[2][0]);
            acc[2][1] = ffma2(b2, q1, acc[2][1]);
            acc[2][2] = ffma2(b2, q2, acc[2][2]);
            float2 a0 = *(const float2*)(Aa + off);
            float2 a1 = *(const float2*)(Aa + off + 2);
            float2 a2 = *(const float2*)(Aa + off + 4);
            acc[3][0] = ffma2(b3, a0, acc[3][0]);
            acc[3][1] = ffma2(b3, a1, acc[3][1]);
            acc[3][2] = ffma2(b3, a2, acc[3][2]);
            float2 h0 = *(const float2*)(Ab + off);
            float2 h1 = *(const float2*)(Ab + off + 2);
            float2 h2 = *(const float2*)(Ab + off + 4);
            acc[4][0] = ffma2(b3, h0, acc[4][0]);
            acc[4][1] = ffma2(b3, h1, acc[4][1]);
            acc[4][2] = ffma2(b3, h2, acc[4][2]);
        }
        if (c < 15) {
            float* d = Bs + ((c + 1) & 1) * 8192;
#pragma unroll
            for (int j = 0; j < 8; j++) {
                int f = t + 256 * j, ks = f >> 7, c4 = (f & 127) * 4;
                *(float4*)&d[ks * 512 + c4] = nb[j];
            }
            __syncthreads();
        }
    }
    __syncthreads();            // all GEMM reads of As done before epi overwrite

#pragma unroll
    for (int pr = 0; pr < 3; pr++) {
        int p = pg + 2 * pr;
        epi[p * 640 + ct]       = acc[0][pr].x;  epi[(p + 1) * 640 + ct]       = acc[0][pr].y;
        epi[p * 640 + 128 + ct] = acc[1][pr].x;  epi[(p + 1) * 640 + 128 + ct] = acc[1][pr].y;
        epi[p * 640 + 256 + ct] = acc[2][pr].x;  epi[(p + 1) * 640 + 256 + ct] = acc[2][pr].y;
        epi[p * 640 + 384 + ct] = acc[3][pr].x;  epi[(p + 1) * 640 + 384 + ct] = acc[3][pr].y;
        epi[p * 640 + 512 + ct] = acc[4][pr].x;  epi[(p + 1) * 640 + 512 + ct] = acc[4][pr].y;
    }
    __syncthreads();

    // epilogue: f gates, c accumulation, node_update
    for (int idx = t; idx < np * Hh; idx += 256) {
        int pl = idx >> 7, m = idx & 127;
        int par = s_par[pl];
        int cA = s_child[2 * pl], cB = s_child[2 * pl + 1];
        const float* Cp = g_C + (size_t)par * NCc;
        float gi = Cp[m]       + epi[pl * 640 + m]       + b_iou[m];
        float go = Cp[128 + m] + epi[pl * 640 + 128 + m] + b_iou[128 + m];
        float gu = Cp[256 + m] + epi[pl * 640 + 256 + m] + b_iou[256 + m];
        float fa = sigf(g_C[(size_t)cA * NCc + 384 + m] + epi[pl * 640 + 384 + m] + b_f[m]);
        float fb = sigf(g_C[(size_t)cB * NCc + 384 + m] + epi[pl * 640 + 512 + m] + b_f[m]);
        float ca = g_c[(size_t)cA * Hh + m]; ca = fminf(fmaxf(ca, -1e14f), 1e14f);
        float cb = g_c[(size_t)cB * Hh + m]; cb = fminf(fmaxf(cb, -1e14f), 1e14f);
        float ct2 = sigf(gi) * tanhf(gu) + fa * ca + fb * cb;
        g_c[(size_t)par * Hh + m] = ct2;
        h[(size_t)par * Hh + m]   = sigf(go) * tanhf(ct2);
    }
}

// ---------------------------------------------------------------------------
extern "C" void kernel_launch(void* const* d_in, const int* in_sizes, int n_in,
                              void* d_out, int out_size) {
    const float* x      = (const float*)d_in[0];
    const float* labels = (const float*)d_in[1];   // [15,6000,1]
    const float* W_iou  = (const float*)d_in[2];
    const float* W_f    = (const float*)d_in[3];
    const float* b_iou  = (const float*)d_in[4];
    const float* b_f    = (const float*)d_in[5];
    const float* U_iou  = (const float*)d_in[6];
    const float* U_f    = (const float*)d_in[7];
    const int*   edges  = (const int*)d_in[8];     // [15,2,6000]
    const int*   order0 = (const int*)d_in[9];
    float* h = (float*)d_out;                      // h lives directly in d_out

    cudaFuncSetAttribute(k_pre,   cudaFuncAttributeMaxDynamicSharedMemorySize, PRE_SMEMB);
    cudaFuncSetAttribute(k_round, cudaFuncAttributeMaxDynamicSharedMemorySize, RND_SMEMB);

    k_trans<<<768, 256>>>(U_iou, U_f, W_iou, W_f);
    k_pre<<<1500, 256, PRE_SMEMB>>>(x);
    k_round0<<<(NPRc * Hh + 255) / 256, 256>>>(h, order0, b_iou);
    for (int ri = 0; ri < 15; ri++)
        k_round<<<RBLK, 256, RND_SMEMB>>>(ri, h, b_iou, b_f, edges, labels);
}

// round 8
// speedup vs baseline: 1.0335x; 1.0335x over previous
#include <cuda_runtime.h>
#include <math.h>

#define Hh   128
#define NPRc 3000
#define EPRc 6000
#define NTOT 48000
#define NCc  512     // C columns: [0,384) iou_x, [384,512) wf_x
#define RBLK 125     // k_round grid: 125 x 24 parents = 3000 exactly

// static scratch (no allocations allowed)
__device__ float g_C[(size_t)NTOT * NCc];   // 98.3 MB
__device__ float g_c[(size_t)NTOT * Hh];    // 24.6 MB
__device__ float g_Ut[256 * 512];           // U^T: [k][row]  (row<384: U_iou, else U_f)
__device__ float g_Wt[128 * 512];           // W^T: [k][row]  (row<384: W_iou, else W_f)

union F2U { float2 f; unsigned long long u; };
__device__ __forceinline__ float2 ffma2(float2 a, float2 b, float2 c) {
    F2U A, B, C2, D;
    A.f = a; B.f = b; C2.f = c;
    asm("fma.rn.f32x2 %0, %1, %2, %3;" : "=l"(D.u) : "l"(A.u), "l"(B.u), "l"(C2.u));
    return D.f;
}
__device__ __forceinline__ float2 spl(float b) { return make_float2(b, b); }
__device__ __forceinline__ float sigf(float x) { return 1.0f / (1.0f + expf(-x)); }

// ---------------------------------------------------------------------------
// One-shot weight transposes, merged (writes coalesced). grid 768.
// ---------------------------------------------------------------------------
__global__ __launch_bounds__(256) void k_trans(const float* __restrict__ U_iou,
                                               const float* __restrict__ U_f,
                                               const float* __restrict__ W_iou,
                                               const float* __restrict__ W_f) {
    int b = blockIdx.x;
    if (b < 512) {
        int idx = b * 256 + threadIdx.x;               // 131072
        int k = idx >> 9, row = idx & 511;
        g_Ut[idx] = (row < 384) ? U_iou[row * 256 + k] : U_f[(row - 384) * 256 + k];
    } else {
        int idx = (b - 512) * 256 + threadIdx.x;       // 65536
        int k = idx >> 9, row = idx & 511;
        g_Wt[idx] = (row < 384) ? W_iou[row * 128 + k] : W_f[(row - 384) * 128 + k];
    }
}

// ---------------------------------------------------------------------------
// k_pre: C[n][0:384] = x @ W_iou^T ; C[n][384:512] = x @ W_f^T
// Tiled GEMM: 32 rows x 512 cols per block, K=128. grid 1500, 2 blocks/SM.
// smem floats: A[128*36] @0 | Bs[2*8*512] @4608 | xs[32*132] @12800 = 17024
// ---------------------------------------------------------------------------
#define PRE_SMEMB (17024 * 4)

__global__ __launch_bounds__(256, 2) void k_pre(const float* __restrict__ x) {
    extern __shared__ float sm[];
    float* A  = sm;           // [k][row], stride 36
    float* Bs = sm + 4608;    // [buf][kk][512]
    float* xs = sm + 12800;   // [row][132]
    int t  = threadIdx.x;
    int r0 = blockIdx.x * 32;

#pragma unroll
    for (int j = 0; j < 4; j++) {                      // stage x coalesced
        int f = t + 256 * j, row = f >> 5, q = f & 31;
        *(float4*)&xs[row * 132 + 4 * q] = *((const float4*)(x + (size_t)(r0 + row) * 128) + q);
    }
    __syncthreads();
#pragma unroll
    for (int j = 0; j < 4; j++) {                      // transpose -> A[k][row]
        int f = t + 256 * j, row = f & 31, q = f >> 5;
        float4 v = *(const float4*)&xs[row * 132 + 4 * q];
        A[(4 * q + 0) * 36 + row] = v.x; A[(4 * q + 1) * 36 + row] = v.y;
        A[(4 * q + 2) * 36 + row] = v.z; A[(4 * q + 3) * 36 + row] = v.w;
    }
#pragma unroll
    for (int j = 0; j < 4; j++) {                      // B chunk 0 (k=0..7), coalesced
        int f = t + 256 * j, ks = f >> 7, c4 = (f & 127) * 4;
        *(float4*)&Bs[ks * 512 + c4] = *(const float4*)&g_Wt[ks * 512 + c4];
    }
    __syncthreads();

    int ct = t & 127;            // cols ct, 128+ct, 256+ct, 384+ct
    int rb = (t >> 7) * 16;      // 16 rows
    float2 acc[4][8];
#pragma unroll
    for (int cc = 0; cc < 4; cc++)
#pragma unroll
        for (int r = 0; r < 8; r++) acc[cc][r] = make_float2(0.f, 0.f);

#pragma unroll 1
    for (int c = 0; c < 16; c++) {                     // 16 chunks x 8 k
        float4 nb[4];
        if (c < 15) {
#pragma unroll
            for (int j = 0; j < 4; j++) {
                int f = t + 256 * j, ks = f >> 7, c4 = (f & 127) * 4;
                nb[j] = *(const float4*)&g_Wt[((c + 1) * 8 + ks) * 512 + c4];
            }
        }
        const float* Bb = Bs + (c & 1) * 4096;
#pragma unroll
        for (int kk = 0; kk < 8; kk++) {
            int kg = c * 8 + kk;
            float2 b0 = spl(Bb[kk * 512 + ct]);
            float2 b1 = spl(Bb[kk * 512 + 128 + ct]);
            float2 b2 = spl(Bb[kk * 512 + 256 + ct]);
            float2 b3 = spl(Bb[kk * 512 + 384 + ct]);
            const float* ap = A + kg * 36 + rb;
#pragma unroll
            for (int g4 = 0; g4 < 4; g4++) {
                float4 av = *(const float4*)(ap + 4 * g4);
                float2 p0 = make_float2(av.x, av.y), p1 = make_float2(av.z, av.w);
                acc[0][2*g4]   = ffma2(b0, p0, acc[0][2*g4]);
                acc[0][2*g4+1] = ffma2(b0, p1, acc[0][2*g4+1]);
                acc[1][2*g4]   = ffma2(b1, p0, acc[1][2*g4]);
                acc[1][2*g4+1] = ffma2(b1, p1, acc[1][2*g4+1]);
                acc[2][2*g4]   = ffma2(b2, p0, acc[2][2*g4]);
                acc[2][2*g4+1] = ffma2(b2, p1, acc[2][2*g4+1]);
                acc[3][2*g4]   = ffma2(b3, p0, acc[3][2*g4]);
                acc[3][2*g4+1] = ffma2(b3, p1, acc[3][2*g4+1]);
            }
        }
        if (c < 15) {
            float* d = Bs + ((c + 1) & 1) * 4096;
#pragma unroll
            for (int j = 0; j < 4; j++) {
                int f = t + 256 * j, ks = f >> 7, c4 = (f & 127) * 4;
                *(float4*)&d[ks * 512 + c4] = nb[j];
            }
            __syncthreads();
        }
    }
#pragma unroll
    for (int cc = 0; cc < 4; cc++) {                   // grid*32 == 48000, no guard
        int col = ct + 128 * cc;
#pragma unroll
        for (int r = 0; r < 8; r++) {
            int row = r0 + rb + 2 * r;
            g_C[(size_t)row * NCc + col]       = acc[cc][r].x;
            g_C[(size_t)(row + 1) * NCc + col] = acc[cc][r].y;
        }
    }
}

// ---------------------------------------------------------------------------
// Round 0: leaves. iou_mid = 0, c = 0.
// ---------------------------------------------------------------------------
__global__ __launch_bounds__(256) void k_round0(float* __restrict__ h,
                                                const int* __restrict__ order0,
                                                const float* __restrict__ b_iou) {
    int idx = blockIdx.x * 256 + threadIdx.x;
    if (idx >= NPRc * Hh) return;
    int j = idx >> 7, m = idx & 127;
    int node = order0[j];
    const float* Cp = g_C + (size_t)node * NCc;
    float gi = Cp[m]       + b_iou[m];
    float go = Cp[128 + m] + b_iou[128 + m];
    float gu = Cp[256 + m] + b_iou[256 + m];
    float ct = sigf(gi) * tanhf(gu);
    g_c[(size_t)node * Hh + m] = ct;
    h[(size_t)node * Hh + m]   = sigf(go) * tanhf(ct);
}

// ---------------------------------------------------------------------------
// One topological round. grid 125 x 384 thr, EXACTLY 24 parents/block.
// Thread (ct = t%128, grp = t/128): 5 col-streams x 8 parents (grp*8).
// A-tile [stream][k][24] smem: s0=gsum, s1=he2_a, s2=he2_b. All A reads are
// LDS.128 broadcasts (pg multiple of 8 -> 32B aligned). B rows from g_Ut,
// double-buffered 16-k chunks. Per SM per k: FFMA 120 cyc == LDS 120 cyc.
// smem floats: As 18432 @0 | Bs 16384 @18432 = 34816
// (hs[48*132]=6336 aliases Bs; epi[24*640]=15360 aliases As after GEMM)
// ---------------------------------------------------------------------------
#define RND_SMEMB (34816 * 4)

__global__ __launch_bounds__(384) void k_round(int ri, float* __restrict__ h,
        const float* __restrict__ b_iou, const float* __restrict__ b_f,
        const int* __restrict__ edges_r, const float* __restrict__ labels) {
    extern __shared__ float sm[];
    float* As  = sm;            // 3*256*24 = 18432
    float* Bs  = sm + 18432;    // 2*16*512 = 16384
    float* hs  = Bs;            // staging alias
    float* epi = sm;            // alias after GEMM
    __shared__ int s_child[48], s_lab[48], s_par[24];

    int t  = threadIdx.x;
    int p0 = (int)blockIdx.x * 24;

    const int*   e_src   = edges_r + ri * 2 * EPRc;
    const int*   e_child = e_src + EPRc;
    const float* labp    = labels + ri * EPRc;

    if (t < 48) {
        int e = 2 * p0 + t;
        s_child[t] = e_child[e];
        s_lab[t]   = (labp[e] != 0.0f) ? 1 : 0;
    }
    if (t >= 64 && t < 88) {
        int pp = t - 64;
        s_par[pp] = e_src[2 * (p0 + pp)];
    }
    __syncthreads();

    // stage 48 child h-rows coalesced (48*32 = 1536 float4 = 4/thread)
#pragma unroll
    for (int j = 0; j < 4; j++) {
        int f = t + 384 * j, e = f >> 5, q = f & 31;
        *(float4*)&hs[e * 132 + 4 * q] = *((const float4*)(h + (size_t)s_child[e] * Hh) + q);
    }
    __syncthreads();
    // scatter into As streams 1,2 with zero complement (k-major, stride 24)
#pragma unroll
    for (int j = 0; j < 4; j++) {
        int f = t + 384 * j, e = f % 48, q = f / 48;   // q in [0,32)
        float4 v = *(const float4*)&hs[e * 132 + 4 * q];
        int p = e >> 1, eo = e & 1, lab = s_lab[e];
        int bh = ((1 + eo) * 256 + lab * 128 + 4 * q) * 24 + p;
        int bz = ((1 + eo) * 256 + (1 - lab) * 128 + 4 * q) * 24 + p;
        As[bh] = v.x; As[bh + 24] = v.y; As[bh + 48] = v.z; As[bh + 72] = v.w;
        As[bz] = 0.f; As[bz + 24] = 0.f; As[bz + 48] = 0.f; As[bz + 72] = 0.f;
    }
    __syncthreads();            // hs (Bs alias) dead from here
    // stream0 = gsum = he2_a + he2_b  (256 k * 6 float4 = 1536 = 4/thread)
#pragma unroll
    for (int j = 0; j < 4; j++) {
        int f = t + 384 * j, k = f / 6, pq = (f % 6) * 4;
        float4 a = *(const float4*)&As[(256 + k) * 24 + pq];
        float4 b = *(const float4*)&As[(512 + k) * 24 + pq];
        *(float4*)&As[k * 24 + pq] = make_float4(a.x + b.x, a.y + b.y, a.z + b.z, a.w + b.w);
    }
    // B chunk 0 (k=0..15): 8192 floats = 2048 float4, guarded
#pragma unroll
    for (int j = 0; j < 6; j++) {
        int f = t + 384 * j;
        if (f < 2048) {
            int ks = f >> 7, c4 = (f & 127) * 4;
            *(float4*)&Bs[ks * 512 + c4] = *(const float4*)&g_Ut[ks * 512 + c4];
        }
    }
    __syncthreads();

    int ct = t & 127;
    int pg = (t >> 7) * 8;      // 0, 8, 16 -> 32B aligned
    const float* Ag = As;
    const float* Aa = As + 6144;
    const float* Ab = As + 12288;
    float2 acc[5][4];
#pragma unroll
    for (int s5 = 0; s5 < 5; s5++)
#pragma unroll
        for (int pr = 0; pr < 4; pr++) acc[s5][pr] = make_float2(0.f, 0.f);

#pragma unroll 1
    for (int c = 0; c < 16; c++) {                     // 16 chunks x 16 k
        float4 nb[6];
        if (c < 15) {
#pragma unroll
            for (int j = 0; j < 6; j++) {
                int f = t + 384 * j;
                if (f < 2048) {
                    int ks = f >> 7, c4 = (f & 127) * 4;
                    nb[j] = *(const float4*)&g_Ut[((c + 1) * 16 + ks) * 512 + c4];
                }
            }
        }
        const float* Bb = Bs + (c & 1) * 8192;
#pragma unroll
        for (int kk = 0; kk < 16; kk++) {
            int kg = c * 16 + kk;
            float2 b0 = spl(Bb[kk * 512 + ct]);
            float2 b1 = spl(Bb[kk * 512 + 128 + ct]);
            float2 b2 = spl(Bb[kk * 512 + 256 + ct]);
            float2 b3 = spl(Bb[kk * 512 + 384 + ct]);
            int off = kg * 24 + pg;
            float4 gA = *(const float4*)(Ag + off);
            float4 gB = *(const float4*)(Ag + off + 4);
            float2 q0 = make_float2(gA.x, gA.y), q1 = make_float2(gA.z, gA.w);
            float2 q2 = make_float2(gB.x, gB.y), q3 = make_float2(gB.z, gB.w);
            acc[0][0] = ffma2(b0, q0, acc[0][0]);
            acc[0][1] = ffma2(b0, q1, acc[0][1]);
            acc[0][2] = ffma2(b0, q2, acc[0][2]);
            acc[0][3] = ffma2(b0, q3, acc[0][3]);
            acc[1][0] = ffma2(b1, q0, acc[1][0]);
            acc[1][1] = ffma2(b1, q1, acc[1][1]);
            acc[1][2] = ffma2(b1, q2, acc[1][2]);
            acc[1][3] = ffma2(b1, q3, acc[1][3]);
            acc[2][0] = ffma2(b2, q0, acc[2][0]);
            acc[2][1] = ffma2(b2, q1, acc[2][1]);
            acc[2][2] = ffma2(b2, q2, acc[2][2]);
            acc[2][3] = ffma2(b2, q3, acc[2][3]);
            float4 aA = *(const float4*)(Aa + off);
            float4 aB = *(const float4*)(Aa + off + 4);
            acc[3][0] = ffma2(b3, make_float2(aA.x, aA.y), acc[3][0]);
            acc[3][1] = ffma2(b3, make_float2(aA.z, aA.w), acc[3][1]);
            acc[3][2] = ffma2(b3, make_float2(aB.x, aB.y), acc[3][2]);
            acc[3][3] = ffma2(b3, make_float2(aB.z, aB.w), acc[3][3]);
            float4 hA = *(const float4*)(Ab + off);
            float4 hB = *(const float4*)(Ab + off + 4);
            acc[4][0] = ffma2(b3, make_float2(hA.x, hA.y), acc[4][0]);
            acc[4][1] = ffma2(b3, make_float2(hA.z, hA.w), acc[4][1]);
            acc[4][2] = ffma2(b3, make_float2(hB.x, hB.y), acc[4][2]);
            acc[4][3] = ffma2(b3, make_float2(hB.z, hB.w), acc[4][3]);
        }
        if (c < 15) {
            float* d = Bs + ((c + 1) & 1) * 8192;
#pragma unroll
            for (int j = 0; j < 6; j++) {
                int f = t + 384 * j;
                if (f < 2048) {
                    int ks = f >> 7, c4 = (f & 127) * 4;
                    *(float4*)&d[ks * 512 + c4] = nb[j];
                }
            }
            __syncthreads();
        }
    }
    __syncthreads();            // all GEMM reads of As done before epi overwrite

#pragma unroll
    for (int pr = 0; pr < 4; pr++) {
        int p = pg + 2 * pr;
        epi[p * 640 + ct]       = acc[0][pr].x;  epi[(p + 1) * 640 + ct]       = acc[0][pr].y;
        epi[p * 640 + 128 + ct] = acc[1][pr].x;  epi[(p + 1) * 640 + 128 + ct] = acc[1][pr].y;
        epi[p * 640 + 256 + ct] = acc[2][pr].x;  epi[(p + 1) * 640 + 256 + ct] = acc[2][pr].y;
        epi[p * 640 + 384 + ct] = acc[3][pr].x;  epi[(p + 1) * 640 + 384 + ct] = acc[3][pr].y;
        epi[p * 640 + 512 + ct] = acc[4][pr].x;  epi[(p + 1) * 640 + 512 + ct] = acc[4][pr].y;
    }
    __syncthreads();

    // epilogue: f gates, c accumulation, node_update (24*128 = 3072 = 8/thread)
#pragma unroll
    for (int j = 0; j < 8; j++) {
        int idx = t + 384 * j;
        int pl = idx >> 7, m = idx & 127;
        int par = s_par[pl];
        int cA = s_child[2 * pl], cB = s_child[2 * pl + 1];
        const float* Cp = g_C + (size_t)par * NCc;
        float gi = Cp[m]       + epi[pl * 640 + m]       + b_iou[m];
        float go = Cp[128 + m] + epi[pl * 640 + 128 + m] + b_iou[128 + m];
        float gu = Cp[256 + m] + epi[pl * 640 + 256 + m] + b_iou[256 + m];
        float fa = sigf(g_C[(size_t)cA * NCc + 384 + m] + epi[pl * 640 + 384 + m] + b_f[m]);
        float fb = sigf(g_C[(size_t)cB * NCc + 384 + m] + epi[pl * 640 + 512 + m] + b_f[m]);
        float ca = g_c[(size_t)cA * Hh + m]; ca = fminf(fmaxf(ca, -1e14f), 1e14f);
        float cb = g_c[(size_t)cB * Hh + m]; cb = fminf(fmaxf(cb, -1e14f), 1e14f);
        float ct2 = sigf(gi) * tanhf(gu) + fa * ca + fb * cb;
        g_c[(size_t)par * Hh + m] = ct2;
        h[(size_t)par * Hh + m]   = sigf(go) * tanhf(ct2);
    }
}

// ---------------------------------------------------------------------------
extern "C" void kernel_launch(void* const* d_in, const int* in_sizes, int n_in,
                              void* d_out, int out_size) {
    const float* x      = (const float*)d_in[0];
    const float* labels = (const float*)d_in[1];   // [15,6000,1]
    const float* W_iou  = (const float*)d_in[2];
    const float* W_f    = (const float*)d_in[3];
    const float* b_iou  = (const float*)d_in[4];
    const float* b_f    = (const float*)d_in[5];
    const float* U_iou  = (const float*)d_in[6];
    const float* U_f    = (const float*)d_in[7];
    const int*   edges  = (const int*)d_in[8];     // [15,2,6000]
    const int*   order0 = (const int*)d_in[9];
    float* h = (float*)d_out;                      // h lives directly in d_out

    cudaFuncSetAttribute(k_pre,   cudaFuncAttributeMaxDynamicSharedMemorySize, PRE_SMEMB);
    cudaFuncSetAttribute(k_round, cudaFuncAttributeMaxDynamicSharedMemorySize, RND_SMEMB);

    k_trans<<<768, 256>>>(U_iou, U_f, W_iou, W_f);
    k_pre<<<1500, 256, PRE_SMEMB>>>(x);
    k_round0<<<(NPRc * Hh + 255) / 256, 256>>>(h, order0, b_iou);
    for (int ri = 0; ri < 15; ri++)
        k_round<<<RBLK, 384, RND_SMEMB>>>(ri, h, b_iou, b_f, edges, labels);
}